// round 2
// baseline (speedup 1.0000x reference)
#include <cuda_runtime.h>
#include <cstdint>

// ElementUpdate: out[n,:] = h_prev[n,:] + W[z[n]] @ m_curr[n,:]
// N=16384, D=128, S=119, z sorted.
// tcgen05 unavailable (harness emits compute_103 PTX, no 'a' features) -> classic
// mma.sync m16n8k8 tf32. 128 CTAs x 128-row tiles; per species segment, masked-A
// MMA accumulating in registers; W[s] staged in SMEM per segment.

static constexpr int D = 128;
static constexpr int TILE_M = 128;
static constexpr int NT = 256;
static constexpr int APAD = 132;                  // float stride, bank-conflict-free
static constexpr int HDR = 2048;
static constexpr int TILE_BYTES = TILE_M * APAD * 4;   // 67584
static constexpr int SMEM_BYTES = HDR + 2 * TILE_BYTES; // 137216

__device__ __forceinline__ uint32_t f2tf32(float f) {
    uint32_t r;
    asm("cvt.rna.tf32.f32 %0, %1;" : "=r"(r) : "f"(f));
    return r;
}

__device__ __forceinline__ void mma_tf32(float* d, const uint32_t* a,
                                         uint32_t b0, uint32_t b1) {
    asm volatile(
        "mma.sync.aligned.m16n8k8.row.col.f32.tf32.tf32.f32 "
        "{%0,%1,%2,%3}, {%4,%5,%6,%7}, {%8,%9}, {%0,%1,%2,%3};"
        : "+f"(d[0]), "+f"(d[1]), "+f"(d[2]), "+f"(d[3])
        : "r"(a[0]), "r"(a[1]), "r"(a[2]), "r"(a[3]), "r"(b0), "r"(b1));
}

__global__ void __launch_bounds__(NT, 1)
element_update_kernel(const float* __restrict__ h_prev,
                      const float* __restrict__ m_curr,
                      const int* __restrict__ atom_types,
                      const float* __restrict__ weight,
                      float* __restrict__ out) {
    extern __shared__ __align__(16) char smem[];
    const int tid = threadIdx.x;
    const int lane = tid & 31;
    const int wid = tid >> 5;
    const int R0 = blockIdx.x * TILE_M;

    int* sCnt  = (int*)(smem + 0);
    int* sOff  = (int*)(smem + 16);
    int* sNseg = (int*)(smem + 32);
    int* sRow  = (int*)(smem + 64);     // up to 129 entries
    int* sSpec = (int*)(smem + 592);    // up to 128 entries
    uint32_t* sA = (uint32_t*)(smem + HDR);
    uint32_t* sW = (uint32_t*)(smem + HDR + TILE_BYTES);

    // ---- species-segment scan over 128 sorted z values (warps 0-3) ----
    bool bd = false; int wpre = 0, zr = 0;
    if (tid < 128) {
        zr = atom_types[R0 + tid];
        int zp = (tid == 0) ? -1 : atom_types[R0 + tid - 1];
        bd = (zp != zr);
        unsigned msk = __ballot_sync(0xffffffffu, bd);
        wpre = __popc(msk & ((1u << lane) - 1u));
        if (lane == 0) sCnt[wid] = __popc(msk);
    }

    // ---- A tile fill (m_curr -> tf32 in SMEM), overlapped before the scan sync ----
    for (int i = tid; i < TILE_M * (D / 4); i += NT) {
        int r = i >> 5, c4 = (i & 31) << 2;
        float4 v = *(const float4*)(m_curr + (size_t)(R0 + r) * D + c4);
        uint4 u;
        u.x = f2tf32(v.x); u.y = f2tf32(v.y); u.z = f2tf32(v.z); u.w = f2tf32(v.w);
        *(uint4*)(sA + r * APAD + c4) = u;
    }
    __syncthreads();
    if (tid == 0) {
        int acc = 0;
        #pragma unroll
        for (int w = 0; w < 4; w++) { sOff[w] = acc; acc += sCnt[w]; }
        *sNseg = acc;
        sRow[acc] = 128;
    }
    __syncthreads();
    if (tid < 128 && bd) {
        int i = sOff[wid] + wpre;
        sRow[i] = tid;
        sSpec[i] = zr;
    }
    __syncthreads();
    const int nseg = *sNseg;

    // ---- warp geometry: warp owns rows [wgr,wgr+32) x cols [wgc,wgc+64) ----
    const int wgr = (wid >> 1) * 32;
    const int wgc = (wid & 1) * 64;
    const int lr = lane >> 2;   // 0..7
    const int lc = lane & 3;    // 0..3

    float acc[2][8][4];
    #pragma unroll
    for (int mt = 0; mt < 2; mt++)
        #pragma unroll
        for (int nt = 0; nt < 8; nt++)
            #pragma unroll
            for (int j = 0; j < 4; j++) acc[mt][nt][j] = 0.f;

    for (int seg = 0; seg < nseg; seg++) {
        const int a = sRow[seg];
        const int b = sRow[seg + 1];
        const int s = sSpec[seg];

        __syncthreads();   // previous segment's compute done before W overwrite
        const float* wsrc = weight + (size_t)s * (D * D);
        for (int i = tid; i < D * (D / 4); i += NT) {
            int r = i >> 5, c4 = (i & 31) << 2;
            float4 v = *(const float4*)(wsrc + (size_t)r * D + c4);
            uint4 u;
            u.x = f2tf32(v.x); u.y = f2tf32(v.y); u.z = f2tf32(v.z); u.w = f2tf32(v.w);
            *(uint4*)(sW + r * APAD + c4) = u;
        }
        __syncthreads();

        if (b > wgr && a < wgr + 32) {
            uint32_t am[2][2];
            #pragma unroll
            for (int mt = 0; mt < 2; mt++)
                #pragma unroll
                for (int h = 0; h < 2; h++) {
                    int r = wgr + 16 * mt + 8 * h + lr;
                    am[mt][h] = (r >= a && r < b) ? 0xffffffffu : 0u;
                }

            #pragma unroll 4
            for (int ks = 0; ks < 16; ks++) {
                const int k0 = ks * 8;
                uint32_t aF[2][4];
                #pragma unroll
                for (int mt = 0; mt < 2; mt++) {
                    const uint32_t* pA = sA + (wgr + 16 * mt + lr) * APAD + k0 + lc;
                    aF[mt][0] = pA[0] & am[mt][0];
                    aF[mt][2] = pA[4] & am[mt][0];
                    aF[mt][1] = pA[8 * APAD] & am[mt][1];
                    aF[mt][3] = pA[8 * APAD + 4] & am[mt][1];
                }
                #pragma unroll
                for (int nt = 0; nt < 8; nt++) {
                    const uint32_t* pB = sW + (wgc + 8 * nt + lr) * APAD + k0 + lc;
                    uint32_t b0 = pB[0];
                    uint32_t b1 = pB[4];
                    mma_tf32(acc[0][nt], aF[0], b0, b1);
                    mma_tf32(acc[1][nt], aF[1], b0, b1);
                }
            }
        }
    }

    // ---- epilogue: acc + h_prev -> out (coalesced float2, full 32B sectors) ----
    #pragma unroll
    for (int mt = 0; mt < 2; mt++)
        #pragma unroll
        for (int h = 0; h < 2; h++) {
            const int r = R0 + wgr + 16 * mt + 8 * h + lr;
            const float* hp = h_prev + (size_t)r * D;
            float* op = out + (size_t)r * D;
            #pragma unroll
            for (int nt = 0; nt < 8; nt++) {
                const int c = wgc + 8 * nt + lc * 2;
                float2 hv = *(const float2*)(hp + c);
                float2 o;
                o.x = hv.x + acc[mt][nt][2 * h + 0];
                o.y = hv.y + acc[mt][nt][2 * h + 1];
                *(float2*)(op + c) = o;
            }
        }
}

extern "C" void kernel_launch(void* const* d_in, const int* in_sizes, int n_in,
                              void* d_out, int out_size) {
    const float* h_prev     = (const float*)d_in[0];
    const float* m_curr     = (const float*)d_in[1];
    const int*   atom_types = (const int*)d_in[2];
    const float* weight     = (const float*)d_in[3];
    float* out = (float*)d_out;

    int n_nodes = in_sizes[0] / D;   // 16384
    int grid = n_nodes / TILE_M;     // 128

    cudaFuncSetAttribute(element_update_kernel,
                         cudaFuncAttributeMaxDynamicSharedMemorySize, SMEM_BYTES);
    element_update_kernel<<<grid, NT, SMEM_BYTES>>>(h_prev, m_curr, atom_types,
                                                    weight, out);
}

// round 3
// speedup vs baseline: 1.0341x; 1.0341x over previous
#include <cuda_runtime.h>
#include <cstdint>

// ElementUpdate: out[n,:] = h_prev[n,:] + W[z[n]] @ m_curr[n,:]
// N=16384, D=128, S=119, z sorted. mma.sync m16n8k8 tf32 (compute_103-safe).
// R3: TILE_M=64, grid=256, 2 CTAs/SM (16 warps/SM) to hide fill/barrier latency
// cross-CTA. Warp tile 16x64 (4 row-warps x 2 col-warps), masked-A per sorted
// species segment, register accumulation across segments.

static constexpr int D = 128;
static constexpr int TILE_M = 64;
static constexpr int NT = 256;
static constexpr int APAD = 132;               // conflict-free float stride
static constexpr int HDR = 1024;
static constexpr int A_BYTES = TILE_M * APAD * 4;   // 33792
static constexpr int W_BYTES = D * APAD * 4;        // 67584
static constexpr int SMEM_BYTES = HDR + A_BYTES + W_BYTES;  // 102400 -> 2 CTAs/SM

__device__ __forceinline__ uint32_t f2tf32(float f) {
    uint32_t r;
    asm("cvt.rna.tf32.f32 %0, %1;" : "=r"(r) : "f"(f));
    return r;
}

__device__ __forceinline__ void mma_tf32(float* d, const uint32_t* a,
                                         uint32_t b0, uint32_t b1) {
    asm volatile(
        "mma.sync.aligned.m16n8k8.row.col.f32.tf32.tf32.f32 "
        "{%0,%1,%2,%3}, {%4,%5,%6,%7}, {%8,%9}, {%0,%1,%2,%3};"
        : "+f"(d[0]), "+f"(d[1]), "+f"(d[2]), "+f"(d[3])
        : "r"(a[0]), "r"(a[1]), "r"(a[2]), "r"(a[3]), "r"(b0), "r"(b1));
}

__global__ void __launch_bounds__(NT, 2)
element_update_kernel(const float* __restrict__ h_prev,
                      const float* __restrict__ m_curr,
                      const int* __restrict__ atom_types,
                      const float* __restrict__ weight,
                      float* __restrict__ out) {
    extern __shared__ __align__(16) char smem[];
    const int tid = threadIdx.x;
    const int lane = tid & 31;
    const int wid = tid >> 5;
    const int R0 = blockIdx.x * TILE_M;

    int* sCnt  = (int*)(smem + 0);
    int* sOff  = (int*)(smem + 16);
    int* sNseg = (int*)(smem + 32);
    int* sRow  = (int*)(smem + 64);     // up to TILE_M+1 entries
    int* sSpec = (int*)(smem + 384);    // up to TILE_M entries
    uint32_t* sA = (uint32_t*)(smem + HDR);
    uint32_t* sW = (uint32_t*)(smem + HDR + A_BYTES);

    // ---- species-segment scan over TILE_M sorted z values (warps 0-1) ----
    bool bd = false; int wpre = 0, zr = 0;
    if (tid < TILE_M) {
        zr = atom_types[R0 + tid];
        int zp = (tid == 0) ? -1 : atom_types[R0 + tid - 1];
        bd = (zp != zr);
        unsigned msk = __ballot_sync(0xffffffffu, bd);
        wpre = __popc(msk & ((1u << lane) - 1u));
        if (lane == 0) sCnt[wid] = __popc(msk);
    }

    // ---- A tile fill (m_curr -> tf32 in SMEM), overlapped with scan ----
    for (int i = tid; i < TILE_M * (D / 4); i += NT) {
        int r = i >> 5, c4 = (i & 31) << 2;
        float4 v = *(const float4*)(m_curr + (size_t)(R0 + r) * D + c4);
        uint4 u;
        u.x = f2tf32(v.x); u.y = f2tf32(v.y); u.z = f2tf32(v.z); u.w = f2tf32(v.w);
        *(uint4*)(sA + r * APAD + c4) = u;
    }
    __syncthreads();
    if (tid == 0) {
        int c0 = sCnt[0], c1 = sCnt[1];
        sOff[0] = 0; sOff[1] = c0;
        *sNseg = c0 + c1;
        sRow[c0 + c1] = TILE_M;
    }
    __syncthreads();
    if (tid < TILE_M && bd) {
        int i = sOff[wid] + wpre;
        sRow[i] = tid;
        sSpec[i] = zr;
    }
    __syncthreads();
    const int nseg = *sNseg;

    // ---- warp geometry: rows [16*wr, 16*wr+16) x cols [64*wc, 64*wc+64) ----
    const int wr = wid >> 1;     // 0..3
    const int wc = wid & 1;      // 0..1
    const int rlo = wr * 16;
    const int lr = lane >> 2;    // 0..7
    const int lc = lane & 3;     // 0..3

    float acc[8][4];
    #pragma unroll
    for (int nt = 0; nt < 8; nt++)
        #pragma unroll
        for (int j = 0; j < 4; j++) acc[nt][j] = 0.f;

    const uint32_t* pAbase = sA + (rlo + lr) * APAD + lc;
    const uint32_t* pBbase = sW + (wc * 64 + lr) * APAD + lc;

    for (int seg = 0; seg < nseg; seg++) {
        const int a = sRow[seg];
        const int b = sRow[seg + 1];
        const int s = sSpec[seg];

        __syncthreads();   // previous segment's compute done before W overwrite
        const float* wsrc = weight + (size_t)s * (D * D);
        for (int i = tid; i < D * (D / 4); i += NT) {
            int r = i >> 5, c4 = (i & 31) << 2;
            float4 v = *(const float4*)(wsrc + (size_t)r * D + c4);
            uint4 u;
            u.x = f2tf32(v.x); u.y = f2tf32(v.y); u.z = f2tf32(v.z); u.w = f2tf32(v.w);
            *(uint4*)(sW + r * APAD + c4) = u;
        }
        __syncthreads();

        if (b > rlo && a < rlo + 16) {
            const int r0 = rlo + lr;
            const uint32_t am0 = (r0 >= a && r0 < b) ? 0xffffffffu : 0u;
            const uint32_t am1 = (r0 + 8 >= a && r0 + 8 < b) ? 0xffffffffu : 0u;

            #pragma unroll 4
            for (int ks = 0; ks < 16; ks++) {
                const int k0 = ks * 8;
                uint32_t aF[4];
                const uint32_t* pA = pAbase + k0;
                aF[0] = pA[0] & am0;
                aF[2] = pA[4] & am0;
                aF[1] = pA[8 * APAD] & am1;
                aF[3] = pA[8 * APAD + 4] & am1;
                #pragma unroll
                for (int nt = 0; nt < 8; nt++) {
                    const uint32_t* pB = pBbase + nt * (8 * APAD) + k0;
                    mma_tf32(acc[nt], aF, pB[0], pB[4]);
                }
            }
        }
    }

    // ---- epilogue: acc + h_prev -> out (coalesced float2, 32B sectors) ----
    #pragma unroll
    for (int h = 0; h < 2; h++) {
        const int r = R0 + rlo + 8 * h + lr;
        const float* hp = h_prev + (size_t)r * D;
        float* op = out + (size_t)r * D;
        #pragma unroll
        for (int nt = 0; nt < 8; nt++) {
            const int c = wc * 64 + 8 * nt + lc * 2;
            float2 hv = *(const float2*)(hp + c);
            float2 o;
            o.x = hv.x + acc[nt][2 * h + 0];
            o.y = hv.y + acc[nt][2 * h + 1];
            *(float2*)(op + c) = o;
        }
    }
}

extern "C" void kernel_launch(void* const* d_in, const int* in_sizes, int n_in,
                              void* d_out, int out_size) {
    const float* h_prev     = (const float*)d_in[0];
    const float* m_curr     = (const float*)d_in[1];
    const int*   atom_types = (const int*)d_in[2];
    const float* weight     = (const float*)d_in[3];
    float* out = (float*)d_out;

    int n_nodes = in_sizes[0] / D;   // 16384
    int grid = n_nodes / TILE_M;     // 256

    cudaFuncSetAttribute(element_update_kernel,
                         cudaFuncAttributeMaxDynamicSharedMemorySize, SMEM_BYTES);
    element_update_kernel<<<grid, NT, SMEM_BYTES>>>(h_prev, m_curr, atom_types,
                                                    weight, out);
}